// round 16
// baseline (speedup 1.0000x reference)
#include <cuda_runtime.h>
#include <cuda_fp16.h>
#include <cstdint>
#include <math.h>

// Problem constants
#define BATCH 4
#define SEQ   2048
#define DMODEL 1024
#define DFFN  2048
#define WIN   64
#define MROWS (BATCH*SEQ)   // 8192
#define EPS   1e-6f

// ---------------- scratch (device globals; no allocation allowed) -------------
__device__ __half g_qk_h[MROWS * 2 * DMODEL];   // q|k fp16 high [M,2048]
__device__ __half g_qk_l[MROWS * 2 * DMODEL];   // q|k fp16 low
__device__ __half g_vh  [MROWS * DMODEL];       // v fp16 [M,1024]
__device__ float  g_xmid [MROWS * DMODEL];
__device__ __half g_atth [MROWS * DMODEL];      // attention out fp16
__device__ __half g_gateh[MROWS * DFFN];        // swiglu gate fp16
// int8 split activations + per-row scales
__device__ int8_t g_xn_h [MROWS * DMODEL];
__device__ int8_t g_xn_l [MROWS * DMODEL];
__device__ int8_t g_att_h[MROWS * DMODEL];
__device__ int8_t g_att_l[MROWS * DMODEL];
__device__ int8_t g_xn2_h[MROWS * DMODEL];
__device__ int8_t g_xn2_l[MROWS * DMODEL];
__device__ int8_t g_gate_h[MROWS * DFFN];
__device__ int8_t g_gate_l[MROWS * DFFN];
__device__ float g_sa_xn [MROWS];
__device__ float g_sa_att[MROWS];
__device__ float g_sa_xn2[MROWS];
__device__ float g_sa_gate[MROWS];
// int8 split transposed weights [N,K] + per-out-row scales
__device__ int8_t g_wqkv_h[3 * DMODEL * DMODEL];
__device__ int8_t g_wqkv_l[3 * DMODEL * DMODEL];
__device__ int8_t g_wo_h  [DMODEL * DMODEL];
__device__ int8_t g_wo_l  [DMODEL * DMODEL];
__device__ int8_t g_w13_h [2 * DFFN * DMODEL];   // interleaved W1|W3
__device__ int8_t g_w13_l [2 * DFFN * DMODEL];
__device__ int8_t g_w2_h  [DMODEL * DFFN];
__device__ int8_t g_w2_l  [DMODEL * DFFN];
__device__ float g_sb_qkv[3 * DMODEL];
__device__ float g_sb_wo [DMODEL];
__device__ float g_sb_w13[2 * DFFN];
__device__ float g_sb_w2 [DMODEL];
__device__ float g_cm    [9216];                 // weight col-max scratch

// ============================= PTX helpers ====================================
__device__ __forceinline__ uint32_t smem_u32(const void* p) {
    uint32_t a;
    asm("{ .reg .u64 t; cvta.to.shared.u64 t, %1; cvt.u32.u64 %0, t; }"
        : "=r"(a) : "l"(p));
    return a;
}
__device__ __forceinline__ uint32_t swz128(uint32_t o) {  // SW128: 128B rows
    return o ^ ((o >> 3) & 0x70);
}
__device__ __forceinline__ void cpasync16(uint32_t dst, const void* src) {
    asm volatile("cp.async.cg.shared.global [%0], [%1], 16;"
                 :: "r"(dst), "l"(__cvta_generic_to_global(src)) : "memory");
}
__device__ __forceinline__ void cp_commit() {
    asm volatile("cp.async.commit_group;" ::: "memory");
}
template <int N>
__device__ __forceinline__ void cp_wait() {
    asm volatile("cp.async.wait_group %0;" :: "n"(N) : "memory");
}
__device__ __forceinline__ void ldsm_x4(uint32_t* r, uint32_t addr) {
    asm volatile("ldmatrix.sync.aligned.m8n8.x4.shared.b16 {%0,%1,%2,%3}, [%4];"
                 : "=r"(r[0]), "=r"(r[1]), "=r"(r[2]), "=r"(r[3]) : "r"(addr));
}
__device__ __forceinline__ void ldsm_x4_trans(uint32_t* r, uint32_t addr) {
    asm volatile("ldmatrix.sync.aligned.m8n8.x4.trans.shared.b16 {%0,%1,%2,%3}, [%4];"
                 : "=r"(r[0]), "=r"(r[1]), "=r"(r[2]), "=r"(r[3]) : "r"(addr));
}
// int8 MMA
__device__ __forceinline__ void mma_s8(int* c, const uint32_t* a,
                                       uint32_t b0, uint32_t b1) {
    asm("mma.sync.aligned.m16n8k32.row.col.s32.s8.s8.s32 "
        "{%0,%1,%2,%3}, {%4,%5,%6,%7}, {%8,%9}, {%0,%1,%2,%3};"
        : "+r"(c[0]), "+r"(c[1]), "+r"(c[2]), "+r"(c[3])
        : "r"(a[0]), "r"(a[1]), "r"(a[2]), "r"(a[3]), "r"(b0), "r"(b1));
}
// fp16 MMA
__device__ __forceinline__ void mma_f16(float* c, const uint32_t* a,
                                        uint32_t b0, uint32_t b1) {
    asm("mma.sync.aligned.m16n8k16.row.col.f32.f16.f16.f32 "
        "{%0,%1,%2,%3}, {%4,%5,%6,%7}, {%8,%9}, {%0,%1,%2,%3};"
        : "+f"(c[0]), "+f"(c[1]), "+f"(c[2]), "+f"(c[3])
        : "r"(a[0]), "r"(a[1]), "r"(a[2]), "r"(a[3]), "r"(b0), "r"(b1));
}

// ================= int8x3 GEMM (128x64, BK=128, 2 stages, 2 CTA/SM) ===========
#define QBM 128
#define QBN 64
#define QBK 128
#define QNS 2
#define QAH 0
#define QAL 16384
#define QBH 32768
#define QBL 40960
#define QSTB 49152
#define QGEMM_SMEM (QNS * QSTB)   // 98304

__device__ __forceinline__ void qgemm_load_stage(
    uint32_t sb,
    const int8_t* __restrict__ Ah, const int8_t* __restrict__ Al,
    const int8_t* __restrict__ Bh, const int8_t* __restrict__ Bl,
    int m0, int n0, int k0, int K, int tid)
{
    {   // A: 128 rows x 128B
        const int row = tid >> 1;
        const int seg = (tid & 1) * 64;
        const uint32_t so = row * 128 + seg;
        const char* pAh = (const char*)(Ah + (size_t)(m0 + row) * K + k0) + seg;
        const char* pAl = (const char*)(Al + (size_t)(m0 + row) * K + k0) + seg;
        #pragma unroll
        for (int s = 0; s < 4; ++s) {
            uint32_t d = swz128(so + s * 16);
            cpasync16(sb + QAH + d, pAh + s * 16);
            cpasync16(sb + QAL + d, pAl + s * 16);
        }
    }
    {   // B: 64 rows x 128B
        const int row = tid >> 2;
        const int seg = (tid & 3) * 32;
        const uint32_t so = row * 128 + seg;
        const char* pBh = (const char*)(Bh + (size_t)(n0 + row) * K + k0) + seg;
        const char* pBl = (const char*)(Bl + (size_t)(n0 + row) * K + k0) + seg;
        #pragma unroll
        for (int s = 0; s < 2; ++s) {
            uint32_t d = swz128(so + s * 16);
            cpasync16(sb + QBH + d, pBh + s * 16);
            cpasync16(sb + QBL + d, pBl + s * 16);
        }
    }
}

__device__ __forceinline__ void qgemm_mainloop(
    int (&hh)[2][4][4], int (&xx)[2][4][4],
    const int8_t* __restrict__ Ah, const int8_t* __restrict__ Al,
    const int8_t* __restrict__ Bh, const int8_t* __restrict__ Bl,
    int m0, int n0, int K, int tid, int wid, int lane, uint32_t base)
{
    const int wm0 = (wid & 3) * 32;
    const int wn0 = (wid >> 2) * 32;
    const int nk = K / QBK;

    #pragma unroll
    for (int i = 0; i < 2; ++i)
        #pragma unroll
        for (int j = 0; j < 4; ++j)
            #pragma unroll
            for (int t = 0; t < 4; ++t) { hh[i][j][t] = 0; xx[i][j][t] = 0; }

    qgemm_load_stage(base, Ah, Al, Bh, Bl, m0, n0, 0, K, tid);
    cp_commit();

    const uint32_t lrow  = (lane & 15);
    const uint32_t lkoff = (lane >> 4) << 4;

    for (int i = 0; i < nk; ++i) {
        cp_wait<0>();
        __syncthreads();

        const int nc = i + 1;
        if (nc < nk)
            qgemm_load_stage(base + (nc & 1) * QSTB,
                             Ah, Al, Bh, Bl, m0, n0, nc * QBK, K, tid);
        cp_commit();

        const uint32_t sb = base + (i & 1) * QSTB;
        #pragma unroll
        for (int ks = 0; ks < 4; ++ks) {
            uint32_t ah[2][4], al[2][4], bhv[2][4], blv[2][4];
            #pragma unroll
            for (int ma = 0; ma < 2; ++ma) {
                uint32_t off = (wm0 + ma * 16 + lrow) * 128 + ks * 32 + lkoff;
                uint32_t ad = sb + swz128(off);
                ldsm_x4(ah[ma], ad + QAH);
                ldsm_x4(al[ma], ad + QAL);
            }
            #pragma unroll
            for (int nt = 0; nt < 2; ++nt) {
                uint32_t off = (wn0 + nt * 16 + lrow) * 128 + ks * 32 + lkoff;
                uint32_t bd = sb + swz128(off);
                ldsm_x4(bhv[nt], bd + QBH);
                ldsm_x4(blv[nt], bd + QBL);
            }
            #pragma unroll
            for (int ma = 0; ma < 2; ++ma)
                #pragma unroll
                for (int nt = 0; nt < 2; ++nt)
                    #pragma unroll
                    for (int h = 0; h < 2; ++h) {
                        const int ng = nt * 2 + h;
                        mma_s8(hh[ma][ng], ah[ma], bhv[nt][h], bhv[nt][2 + h]);
                        mma_s8(xx[ma][ng], ah[ma], blv[nt][h], blv[nt][2 + h]);
                        mma_s8(xx[ma][ng], al[ma], bhv[nt][h], bhv[nt][2 + h]);
                    }
        }
    }
}

__device__ __forceinline__ float qcomb(int h, int x) {
    return fmaf(16384.0f, (float)h, 128.0f * (float)x);
}

__global__ __launch_bounds__(256)
void qgemm(const int8_t* __restrict__ Ah, const int8_t* __restrict__ Al,
           const int8_t* __restrict__ Bh, const int8_t* __restrict__ Bl,
           const float* __restrict__ sa, const float* __restrict__ sb,
           const float* __restrict__ R, float* __restrict__ C,
           int N, int K)
{
    extern __shared__ char smem[];
    const int tid  = threadIdx.x;
    const int wid  = tid >> 5;
    const int lane = tid & 31;
    const int m0 = blockIdx.y * QBM;
    const int n0 = blockIdx.x * QBN;
    const uint32_t base = smem_u32(smem);

    int hh[2][4][4], xx[2][4][4];
    qgemm_mainloop(hh, xx, Ah, Al, Bh, Bl, m0, n0, K, tid, wid, lane, base);

    const int wm0 = (wid & 3) * 32;
    const int wn0 = (wid >> 2) * 32;
    const int mrow = lane >> 2;
    const int nc2  = (lane & 3) * 2;
    #pragma unroll
    for (int ma = 0; ma < 2; ++ma) {
        const int mA = m0 + wm0 + ma * 16 + mrow;
        const int mB = mA + 8;
        const float saA = sa[mA], saB = sa[mB];
        #pragma unroll
        for (int ng = 0; ng < 4; ++ng) {
            const int n = n0 + wn0 + ng * 8 + nc2;
            float2 sbv = *reinterpret_cast<const float2*>(sb + n);
            float2 v0, v1;
            v0.x = saA * sbv.x * qcomb(hh[ma][ng][0], xx[ma][ng][0]);
            v0.y = saA * sbv.y * qcomb(hh[ma][ng][1], xx[ma][ng][1]);
            v1.x = saB * sbv.x * qcomb(hh[ma][ng][2], xx[ma][ng][2]);
            v1.y = saB * sbv.y * qcomb(hh[ma][ng][3], xx[ma][ng][3]);
            size_t o0 = (size_t)mA * N + n;
            size_t o1 = (size_t)mB * N + n;
            if (R) {
                float2 r0 = *reinterpret_cast<const float2*>(R + o0);
                float2 r1 = *reinterpret_cast<const float2*>(R + o1);
                v0.x += r0.x; v0.y += r0.y;
                v1.x += r1.x; v1.y += r1.y;
            }
            *reinterpret_cast<float2*>(C + o0) = v0;
            *reinterpret_cast<float2*>(C + o1) = v1;
        }
    }
}

// QKV GEMM: q,k columns (n<2048) -> fp16 h/l pairs; v columns -> fp16 single.
__global__ __launch_bounds__(256)
void qgemm_qkv(const int8_t* __restrict__ Ah, const int8_t* __restrict__ Al,
               const int8_t* __restrict__ Bh, const int8_t* __restrict__ Bl,
               const float* __restrict__ sa, const float* __restrict__ sb,
               __half* __restrict__ qkh, __half* __restrict__ qkl,
               __half* __restrict__ vh, int K)
{
    extern __shared__ char smem[];
    const int tid  = threadIdx.x;
    const int wid  = tid >> 5;
    const int lane = tid & 31;
    const int m0 = blockIdx.y * QBM;
    const int n0 = blockIdx.x * QBN;
    const uint32_t base = smem_u32(smem);

    int hh[2][4][4], xx[2][4][4];
    qgemm_mainloop(hh, xx, Ah, Al, Bh, Bl, m0, n0, K, tid, wid, lane, base);

    const int wm0 = (wid & 3) * 32;
    const int wn0 = (wid >> 2) * 32;
    const int mrow = lane >> 2;
    const int nc2  = (lane & 3) * 2;
    const bool isv = (n0 >= 2048);
    #pragma unroll
    for (int ma = 0; ma < 2; ++ma) {
        const int mA = m0 + wm0 + ma * 16 + mrow;
        const int mB = mA + 8;
        const float saA = sa[mA], saB = sa[mB];
        #pragma unroll
        for (int ng = 0; ng < 4; ++ng) {
            const int n = n0 + wn0 + ng * 8 + nc2;
            float2 sbv = *reinterpret_cast<const float2*>(sb + n);
            float2 v0, v1;
            v0.x = saA * sbv.x * qcomb(hh[ma][ng][0], xx[ma][ng][0]);
            v0.y = saA * sbv.y * qcomb(hh[ma][ng][1], xx[ma][ng][1]);
            v1.x = saB * sbv.x * qcomb(hh[ma][ng][2], xx[ma][ng][2]);
            v1.y = saB * sbv.y * qcomb(hh[ma][ng][3], xx[ma][ng][3]);
            if (!isv) {
                size_t o0 = (size_t)mA * 2048 + n;
                size_t o1 = (size_t)mB * 2048 + n;
                __half2 h0, l0, h1, l1;
                h0.x = __float2half_rn(v0.x); h0.y = __float2half_rn(v0.y);
                l0.x = __float2half_rn(v0.x - __half2float(h0.x));
                l0.y = __float2half_rn(v0.y - __half2float(h0.y));
                h1.x = __float2half_rn(v1.x); h1.y = __float2half_rn(v1.y);
                l1.x = __float2half_rn(v1.x - __half2float(h1.x));
                l1.y = __float2half_rn(v1.y - __half2float(h1.y));
                *reinterpret_cast<__half2*>(qkh + o0) = h0;
                *reinterpret_cast<__half2*>(qkl + o0) = l0;
                *reinterpret_cast<__half2*>(qkh + o1) = h1;
                *reinterpret_cast<__half2*>(qkl + o1) = l1;
            } else {
                size_t o0 = (size_t)mA * 1024 + (n - 2048);
                size_t o1 = (size_t)mB * 1024 + (n - 2048);
                __half2 a, bq;
                a.x  = __float2half_rn(v0.x); a.y  = __float2half_rn(v0.y);
                bq.x = __float2half_rn(v1.x); bq.y = __float2half_rn(v1.y);
                *reinterpret_cast<__half2*>(vh + o0) = a;
                *reinterpret_cast<__half2*>(vh + o1) = bq;
            }
        }
    }
}

// W13 interleaved + fused SwiGLU: writes gate fp16 [M, DFFN].
__global__ __launch_bounds__(256)
void qgemm_swiglu(const int8_t* __restrict__ Ah, const int8_t* __restrict__ Al,
                  const int8_t* __restrict__ Bh, const int8_t* __restrict__ Bl,
                  const float* __restrict__ sa, const float* __restrict__ sb,
                  __half* __restrict__ gate, int K)
{
    extern __shared__ char smem[];
    const int tid  = threadIdx.x;
    const int wid  = tid >> 5;
    const int lane = tid & 31;
    const int m0 = blockIdx.y * QBM;
    const int n0 = blockIdx.x * QBN;
    const uint32_t base = smem_u32(smem);

    int hh[2][4][4], xx[2][4][4];
    qgemm_mainloop(hh, xx, Ah, Al, Bh, Bl, m0, n0, K, tid, wid, lane, base);

    const int wm0 = (wid & 3) * 32;
    const int wn0 = (wid >> 2) * 32;
    const int mrow = lane >> 2;
    const int nc2  = (lane & 3) * 2;
    const int gbase = (n0 + wn0) >> 1;
    #pragma unroll
    for (int ma = 0; ma < 2; ++ma) {
        const int mA = m0 + wm0 + ma * 16 + mrow;
        const int mB = mA + 8;
        const float saA = sa[mA], saB = sa[mB];
        #pragma unroll
        for (int g = 0; g < 2; ++g) {
            const int p1 = n0 + wn0 + 16 * g + nc2;
            const int p3 = p1 + 8;
            float2 sb1 = *reinterpret_cast<const float2*>(sb + p1);
            float2 sb3 = *reinterpret_cast<const float2*>(sb + p3);
            const int gcol = gbase + 8 * g + nc2;
            const int n1 = 2 * g, n3 = 2 * g + 1;
            {
                float a0 = saA * sb1.x * qcomb(hh[ma][n1][0], xx[ma][n1][0]);
                float a1 = saA * sb1.y * qcomb(hh[ma][n1][1], xx[ma][n1][1]);
                float c0 = saA * sb3.x * qcomb(hh[ma][n3][0], xx[ma][n3][0]);
                float c1 = saA * sb3.y * qcomb(hh[ma][n3][1], xx[ma][n3][1]);
                __half2 o;
                o.x = __float2half_rn(a0 / (1.0f + __expf(-a0)) * c0);
                o.y = __float2half_rn(a1 / (1.0f + __expf(-a1)) * c1);
                *reinterpret_cast<__half2*>(gate + (size_t)mA * DFFN + gcol) = o;
            }
            {
                float a0 = saB * sb1.x * qcomb(hh[ma][n1][2], xx[ma][n1][2]);
                float a1 = saB * sb1.y * qcomb(hh[ma][n1][3], xx[ma][n1][3]);
                float c0 = saB * sb3.x * qcomb(hh[ma][n3][2], xx[ma][n3][2]);
                float c1 = saB * sb3.y * qcomb(hh[ma][n3][3], xx[ma][n3][3]);
                __half2 o;
                o.x = __float2half_rn(a0 / (1.0f + __expf(-a0)) * c0);
                o.y = __float2half_rn(a1 / (1.0f + __expf(-a1)) * c1);
                *reinterpret_cast<__half2*>(gate + (size_t)mB * DFFN + gcol) = o;
            }
        }
    }
}

// ---------------- 15-bit quantization helper ----------------------------------
__device__ __forceinline__ void quant15(float v, float invq, int8_t& h, int8_t& l) {
    float t  = rintf(v * invq);
    float th = rintf(t * 0.0078125f);
    h = (int8_t)(int)th;
    l = (int8_t)(int)(t - 128.0f * th);
}

// ============ weight col-max, 7 jobs ==========================================
#define NWJOBS 7
struct CmJobs {
    const float* src[NWJOBS];
    int K[NWJOBS];
    int N[NWJOBS];
    int col_off[NWJOBS + 1];
};
__global__ void colmax_kernel(CmJobs jb, float* cm)
{
    int c = blockIdx.x * 256 + threadIdx.x;
    int j = 0;
    #pragma unroll
    for (int i = 0; i < NWJOBS; ++i)
        if (c >= jb.col_off[i + 1]) j = i + 1;
    const int n = c - jb.col_off[j];
    const int K = jb.K[j], N = jb.N[j];
    const float* W = jb.src[j];
    float m = 0.0f;
    for (int k = 0; k < K; ++k)
        m = fmaxf(m, fabsf(W[(size_t)k * N + n]));
    cm[c] = m;
}

// ============ weight transpose + int8 split quant =============================
struct WJobs {
    const float* src[NWJOBS];
    int8_t* dsth[NWJOBS];
    int8_t* dstl[NWJOBS];
    float* sbp[NWJOBS];
    int K[NWJOBS];
    int N[NWJOBS];
    int mode[NWJOBS];
    int tile_off[NWJOBS + 1];
    int col_off[NWJOBS];
};
__global__ void wsplit_all_kernel(WJobs jb, const float* cm)
{
    __shared__ float t[32][33];
    int tile = blockIdx.x;
    int j = 0;
    #pragma unroll
    for (int i = 0; i < NWJOBS; ++i)
        if (tile >= jb.tile_off[i + 1]) j = i + 1;
    const int lt   = tile - jb.tile_off[j];
    const int K    = jb.K[j];
    const int N    = jb.N[j];
    const int mode = jb.mode[j];
    const float* W = jb.src[j];
    int8_t* Th     = jb.dsth[j];
    int8_t* Tl     = jb.dstl[j];
    const int ntx  = N >> 5;
    const int n0 = (lt % ntx) * 32;
    const int k0 = (lt / ntx) * 32;

    int tx = threadIdx.x & 31, ty = threadIdx.x >> 5;
    #pragma unroll
    for (int r = ty; r < 32; r += 8)
        t[r][tx] = W[(size_t)(k0 + r) * N + n0 + tx];
    __syncthreads();
    #pragma unroll
    for (int r = ty; r < 32; r += 8) {
        float v = t[tx][r];
        int n = n0 + r;
        int p = (mode == 0) ? n : (16 * (n >> 3) + (n & 7) + ((mode == 2) ? 8 : 0));
        float mx = cm[jb.col_off[j] + n];
        float invq = (mx > 0.0f) ? (16256.0f / mx) : 0.0f;
        int8_t h, l;
        quant15(v, invq, h, l);
        size_t o = (size_t)p * K + k0 + tx;
        Th[o] = h; Tl[o] = l;
        if (k0 + tx == 0) jb.sbp[j][p] = mx * (1.0f / 16256.0f);
    }
}

// ---------------- RMSNorm + int8 split quant ----------------------------------
__global__ void rmsnorm_quant_kernel(const float* __restrict__ x,
                                     const float* __restrict__ w,
                                     int8_t* __restrict__ oh,
                                     int8_t* __restrict__ ol,
                                     float* __restrict__ sa) {
    const int D = DMODEL;
    size_t row = blockIdx.x;
    const float4* xr = reinterpret_cast<const float4*>(x + row * D);
    const float4* wr = reinterpret_cast<const float4*>(w);

    int tid = threadIdx.x;
    float4 xv = xr[tid];
    float4 wv = wr[tid];
    float p0 = xv.x * wv.x, p1 = xv.y * wv.y, p2 = xv.z * wv.z, p3 = xv.w * wv.w;
    float ss = xv.x*xv.x + xv.y*xv.y + xv.z*xv.z + xv.w*xv.w;
    float mx = fmaxf(fmaxf(fabsf(p0), fabsf(p1)), fmaxf(fabsf(p2), fabsf(p3)));

    #pragma unroll
    for (int off = 16; off; off >>= 1) {
        ss += __shfl_xor_sync(0xffffffffu, ss, off);
        mx = fmaxf(mx, __shfl_xor_sync(0xffffffffu, mx, off));
    }
    __shared__ float reds[8], redm[8];
    int lane = tid & 31, warp = tid >> 5;
    if (lane == 0) { reds[warp] = ss; redm[warp] = mx; }
    __syncthreads();
    if (tid < 32) {
        float v = (tid < 8) ? reds[tid] : 0.0f;
        float m = (tid < 8) ? redm[tid] : 0.0f;
        #pragma unroll
        for (int off = 4; off; off >>= 1) {
            v += __shfl_xor_sync(0xffffffffu, v, off);
            m = fmaxf(m, __shfl_xor_sync(0xffffffffu, m, off));
        }
        if (tid == 0) {
            float inv = rsqrtf(v * (1.0f / D) + EPS);
            reds[0] = inv;
            redm[0] = m;
            sa[row] = inv * m * (1.0f / 16256.0f);
        }
    }
    __syncthreads();
    float m = redm[0];
    float invq = (m > 0.0f) ? (16256.0f / m) : 0.0f;

    int8_t hv[4], lv[4];
    quant15(p0, invq, hv[0], lv[0]);
    quant15(p1, invq, hv[1], lv[1]);
    quant15(p2, invq, hv[2], lv[2]);
    quant15(p3, invq, hv[3], lv[3]);
    size_t b = row * D + tid * 4;
    *reinterpret_cast<char4*>(oh + b) = make_char4(hv[0], hv[1], hv[2], hv[3]);
    *reinterpret_cast<char4*>(ol + b) = make_char4(lv[0], lv[1], lv[2], lv[3]);
}

// ---------------- per-row quant pass (fp16 input) ------------------------------
__global__ void quant_rows_h_kernel(const __half* __restrict__ src, int D,
                                    int8_t* __restrict__ oh, int8_t* __restrict__ ol,
                                    float* __restrict__ sa)
{
    size_t row = blockIdx.x;
    const uint2* sr = reinterpret_cast<const uint2*>(src + row * D);  // 4 halves
    int tid = threadIdx.x;
    const int iters = D / 1024;   // 1 or 2

    float f[2][4];
    float mx = 0.0f;
    #pragma unroll
    for (int it = 0; it < 2; ++it) {
        if (it < iters) {
            uint2 u = sr[tid + it * 256];
            __half2 a = *reinterpret_cast<__half2*>(&u.x);
            __half2 b = *reinterpret_cast<__half2*>(&u.y);
            f[it][0] = __half2float(a.x); f[it][1] = __half2float(a.y);
            f[it][2] = __half2float(b.x); f[it][3] = __half2float(b.y);
            mx = fmaxf(mx, fmaxf(fmaxf(fabsf(f[it][0]), fabsf(f[it][1])),
                                 fmaxf(fabsf(f[it][2]), fabsf(f[it][3]))));
        }
    }
    #pragma unroll
    for (int off = 16; off; off >>= 1)
        mx = fmaxf(mx, __shfl_xor_sync(0xffffffffu, mx, off));
    __shared__ float redm[8];
    int lane = tid & 31, warp = tid >> 5;
    if (lane == 0) redm[warp] = mx;
    __syncthreads();
    if (tid < 32) {
        float m = (tid < 8) ? redm[tid] : 0.0f;
        #pragma unroll
        for (int off = 4; off; off >>= 1)
            m = fmaxf(m, __shfl_xor_sync(0xffffffffu, m, off));
        if (tid == 0) {
            redm[0] = m;
            sa[row] = m * (1.0f / 16256.0f);
        }
    }
    __syncthreads();
    float m = redm[0];
    float invq = (m > 0.0f) ? (16256.0f / m) : 0.0f;

    #pragma unroll
    for (int it = 0; it < 2; ++it) {
        if (it < iters) {
            int8_t hv[4], lv[4];
            quant15(f[it][0], invq, hv[0], lv[0]);
            quant15(f[it][1], invq, hv[1], lv[1]);
            quant15(f[it][2], invq, hv[2], lv[2]);
            quant15(f[it][3], invq, hv[3], lv[3]);
            size_t b = row * D + (tid + it * 256) * 4;
            *reinterpret_cast<char4*>(oh + b) = make_char4(hv[0], hv[1], hv[2], hv[3]);
            *reinterpret_cast<char4*>(ol + b) = make_char4(lv[0], lv[1], lv[2], lv[3]);
        }
    }
}

// ---------------- Attention: fp16-MMA scores + fp16-MMA PV --------------------
#define ATQ   32
#define ASPAD 132
#define AS_BYTES (ATQ * ASPAD * 4)
#define AP_OFF  16896                  // P fp16 [32][136] pitch 272B
#define AST_OFF 25600                  // stage area (2 x 40960)
#define ASTG  40960
#define AQH 0
#define AQL 4096
#define AKH 8192
#define AKL 24576
#define ATTN_SMEM (AST_OFF + 2 * ASTG)   // 107520 B

__device__ __forceinline__ void attn_load_chunk(
    uint32_t st, const __half* __restrict__ qkh, const __half* __restrict__ qkl,
    size_t rowbase, int t0, int jlo, int span, int dc, int tid)
{
    const int d0 = dc * 64;
    {
        const int row = tid >> 3;
        const int seg = (tid & 7) * 16;
        const uint32_t d = swz128(row * 128 + seg);
        const char* ph = (const char*)(qkh + (rowbase + t0 + row) * 2048 + d0) + seg;
        const char* pl = (const char*)(qkl + (rowbase + t0 + row) * 2048 + d0) + seg;
        cpasync16(st + AQH + d, ph);
        cpasync16(st + AQL + d, pl);
    }
    {
        const int seg = (tid & 7) * 16;
        for (int r = tid >> 3; r < span; r += 32) {
            const uint32_t d = swz128(r * 128 + seg);
            const char* ph = (const char*)(qkh + (rowbase + jlo + r) * 2048 + 1024 + d0) + seg;
            const char* pl = (const char*)(qkl + (rowbase + jlo + r) * 2048 + 1024 + d0) + seg;
            cpasync16(st + AKH + d, ph);
            cpasync16(st + AKL + d, pl);
        }
    }
}

__device__ __forceinline__ void attn_load_v(
    uint32_t vb, const __half* __restrict__ vh,
    size_t rowbase, int jlo, int span, int d0, int tid)
{
    for (int idx = tid; idx < span * 16; idx += 256) {
        const int r = idx >> 4;
        const int s = idx & 15;
        const char* p = (const char*)(vh + (rowbase + jlo + r) * 1024 + d0) + s * 16;
        cpasync16(vb + r * 272 + s * 16, p);
    }
}

__global__ __launch_bounds__(256)
void attn_mma_kernel(const __half* __restrict__ qkh, const __half* __restrict__ qkl,
                     const __half* __restrict__ vh, __half* __restrict__ atth)
{
    extern __shared__ char smraw[];
    float* S = (float*)smraw;
    const uint32_t smb = smem_u32(smraw);
    const uint32_t sbase = smb + AST_OFF;

    const int tid  = threadIdx.x;
    const int wid  = tid >> 5;
    const int lane = tid & 31;
    const int blk  = blockIdx.x;
    const int b    = blk >> 6;
    const int t0   = (blk & 63) * ATQ;
    const int jlo  = (t0 >= WIN) ? (t0 - (WIN - 1)) : 0;   // clamped
    const int span = t0 + ATQ - jlo;          // 32, 64, or 95
    const size_t rowbase = (size_t)b * SEQ;
    const float scale = 0.03125f;

    // ---- phase 1: scores via fp16x3 mma ----
    const int wm = (wid & 1) * 16;
    const int wn = (wid >> 1) * 32;
    const uint32_t lrow  = (lane & 15);
    const uint32_t lkoff = (lane >> 4) << 4;

    float acc[4][4];
    #pragma unroll
    for (int i = 0; i < 4; ++i)
        #pragma unroll
        for (int t = 0; t < 4; ++t) acc[i][t] = 0.0f;

    attn_load_chunk(sbase, qkh, qkl, rowbase, t0, jlo, span, 0, tid);
    cp_commit();

    for (int dc = 0; dc < 16; ++dc) {
        cp_wait<0>();
        __syncthreads();
        if (dc + 1 < 16) {
            attn_load_chunk(sbase + ((dc + 1) & 1) * ASTG,
                            qkh, qkl, rowbase, t0, jlo, span, dc + 1, tid);
            cp_commit();
        }
        const uint32_t st = sbase + (dc & 1) * ASTG;
        #pragma unroll
        for (int ks = 0; ks < 4; ++ks) {
            uint32_t ah[4], al[4], bh[2][4], bl[2][4];
            uint32_t offA = (wm + lrow) * 128 + ks * 32 + lkoff;
            ldsm_x4(ah, st + AQH + swz128(offA));
            ldsm_x4(al, st + AQL + swz128(offA));
            #pragma unroll
            for (int nt = 0; nt < 2; ++nt) {
                uint32_t offB = (wn + nt * 16 + lrow) * 128 + ks * 32 + lkoff;
                ldsm_x4(bh[nt], st + AKH + swz128(offB));
                ldsm_x4(bl[nt], st + AKL + swz128(offB));
            }
            #pragma unroll
            for (int nt = 0; nt < 2; ++nt)
                #pragma unroll
                for (int h = 0; h < 2; ++h) {
                    const int ng = nt * 2 + h;
                    mma_f16(acc[ng], ah, bh[nt][h], bh[nt][2 + h]);
                    mma_f16(acc[ng], ah, bl[nt][h], bl[nt][2 + h]);
                    mma_f16(acc[ng], al, bh[nt][h], bh[nt][2 + h]);
                }
        }
    }

    // store scores to S
    {
        const int mrow = lane >> 2;
        const int nc2  = (lane & 3) * 2;
        #pragma unroll
        for (int ng = 0; ng < 4; ++ng) {
            const int n = wn + ng * 8 + nc2;
            S[(wm + mrow    ) * ASPAD + n    ] = acc[ng][0] * scale;
            S[(wm + mrow    ) * ASPAD + n + 1] = acc[ng][1] * scale;
            S[(wm + mrow + 8) * ASPAD + n    ] = acc[ng][2] * scale;
            S[(wm + mrow + 8) * ASPAD + n + 1] = acc[ng][3] * scale;
        }
    }
    __syncthreads();

    // ---- phase 2: softmax + write P fp16 ----
    if (tid < ATQ) {
        const int qi  = tid;
        const int ti  = t0 + qi;
        const int wlo = ((ti >= WIN - 1) ? ti - (WIN - 1) : 0) - jlo;
        const int whi = ti - jlo;
        float* row = S + qi * ASPAD;
        float m = -1e30f;
        for (int jj = wlo; jj <= whi; ++jj) m = fmaxf(m, row[jj]);
        float sum = 0.0f;
        for (int jj = wlo; jj <= whi; ++jj) {
            float e = __expf(row[jj] - m);
            row[jj] = e;
            sum += e;
        }
        float inv = 1.0f / sum;
        __half* Prow = (__half*)(smraw + AP_OFF) + qi * 136;
        for (int jj = 0; jj < 128; ++jj) {
            float p = (jj >= wlo && jj <= whi) ? row[jj] * inv : 0.0f;
            Prow[jj] = __float2half_rn(p);
        }
    }
    __syncthreads();

    // ---- phase 3: PV via fp16 mma ----
    {
        float4 z = make_float4(0.f, 0.f, 0.f, 0.f);
        const int npad = 128 - span;
        for (int idx = tid; idx < npad * 34; idx += 256) {
            int bufr = idx / 17;
            int s    = idx % 17;
            int buf  = bufr & 1;
            int r    = span + (bufr >> 1);
            *reinterpret_cast<float4*>(smraw + AST_OFF + buf * ASTG + r * 272 + s * 16) = z;
        }
    }
    attn_load_v(sbase, vh, rowbase, jlo, span, 0, tid);
    cp_commit();

    const uint32_t Pbase = smb + AP_OFF;
    const int wmP = (wid & 1) * 16;
    const int wnV = (wid >> 1) * 32;

    for (int vc = 0; vc < 8; ++vc) {
        cp_wait<0>();
        __syncthreads();
        if (vc + 1 < 8) {
            attn_load_v(sbase + ((vc + 1) & 1) * ASTG,
                        vh, rowbase, jlo, span, (vc + 1) * 128, tid);
            cp_commit();
        }
        const uint32_t Vb = sbase + (vc & 1) * ASTG;

        float oacc[4][4];
        #pragma unroll
        for (int i = 0; i < 4; ++i)
            #pragma unroll
            for (int t = 0; t < 4; ++t) oacc[i][t] = 0.0f;

        #pragma unroll
        for (int ks = 0; ks < 8; ++ks) {
            uint32_t ap[4];
            ldsm_x4(ap, Pbase + (wmP + (lane & 15)) * 272 + ks * 32 + ((lane >> 4) << 4));
            uint32_t bt[2][4];
            #pragma unroll
            for (int nt = 0; nt < 2; ++nt)
                ldsm_x4_trans(bt[nt],
                    Vb + (ks * 16 + (lane & 15)) * 272 + (wnV + nt * 16) * 2 + ((lane >> 4) << 4));
            #pragma unroll
            for (int nt = 0; nt < 2; ++nt) {
                mma_f16(oacc[nt * 2],     ap, bt[nt][0], bt[nt][1]);
                mma_f16(oacc[nt * 2 + 1], ap, bt[nt][2], bt[nt][3]);
            }
        }

        const int mrow = lane >> 2;
        const int nc2  = (lane & 3) * 2;
        #pragma unroll
        for (int ng = 0; ng < 4; ++ng) {
            const int d = vc * 128 + wnV + ng * 8 + nc2;
            size_t o0 = (rowbase + t0 + wmP + mrow) * DMODEL + d;
            size_t o1 = o0 + (size_t)8 * DMODEL;
            __half2 h0, h1;
            h0.x = __float2half_rn(oacc[ng][0]); h0.y = __float2half_rn(oacc[ng][1]);
            h1.x = __float2half_rn(oacc[ng][2]); h1.y = __float2half_rn(oacc[ng][3]);
            *reinterpret_cast<__half2*>(atth + o0) = h0;
            *reinterpret_cast<__half2*>(atth + o1) = h1;
        }
    }
}

// ---------------- launch -------------------------------------------------------
extern "C" void kernel_launch(void* const* d_in, const int* in_sizes, int n_in,
                              void* d_out, int out_size) {
    const float* x       = (const float*)d_in[0];
    const float* norm1_w = (const float*)d_in[1];
    const float* norm2_w = (const float*)d_in[2];
    const float* Wq      = (const float*)d_in[3];
    const float* Wk      = (const float*)d_in[4];
    const float* Wv      = (const float*)d_in[5];
    const float* Wo      = (const float*)d_in[6];
    const float* W1      = (const float*)d_in[7];
    const float* W2      = (const float*)d_in[8];
    const float* W3      = (const float*)d_in[9];
    float* out = (float*)d_out;

    float *p_xmid, *p_cm;
    __half *p_qkh, *p_qkl, *p_vh, *p_atth, *p_gateh;
    cudaGetSymbolAddress((void**)&p_qkh,   g_qk_h);
    cudaGetSymbolAddress((void**)&p_qkl,   g_qk_l);
    cudaGetSymbolAddress((void**)&p_vh,    g_vh);
    cudaGetSymbolAddress((void**)&p_xmid,  g_xmid);
    cudaGetSymbolAddress((void**)&p_atth,  g_atth);
    cudaGetSymbolAddress((void**)&p_gateh, g_gateh);
    cudaGetSymbolAddress((void**)&p_cm,    g_cm);

    int8_t *xn_h, *xn_l, *att_h, *att_l, *xn2_h, *xn2_l, *gate_h, *gate_l;
    cudaGetSymbolAddress((void**)&xn_h,  g_xn_h);
    cudaGetSymbolAddress((void**)&xn_l,  g_xn_l);
    cudaGetSymbolAddress((void**)&att_h, g_att_h);
    cudaGetSymbolAddress((void**)&att_l, g_att_l);
    cudaGetSymbolAddress((void**)&xn2_h, g_xn2_h);
    cudaGetSymbolAddress((void**)&xn2_l, g_xn2_l);
    cudaGetSymbolAddress((void**)&gate_h, g_gate_h);
    cudaGetSymbolAddress((void**)&gate_l, g_gate_l);

    float *sa_xn, *sa_att, *sa_xn2, *sa_gate;
    cudaGetSymbolAddress((void**)&sa_xn,   g_sa_xn);
    cudaGetSymbolAddress((void**)&sa_att,  g_sa_att);
    cudaGetSymbolAddress((void**)&sa_xn2,  g_sa_xn2);
    cudaGetSymbolAddress((void**)&sa_gate, g_sa_gate);

    int8_t *wqkv_h, *wqkv_l, *wo_h, *wo_l, *w13_h, *w13_l, *w2_h, *w2_l;
    cudaGetSymbolAddress((void**)&wqkv_h, g_wqkv_h);
    cudaGetSymbolAddress((void**)&wqkv_l, g_wqkv_l);
    cudaGetSymbolAddress((void**)&wo_h,   g_wo_h);
    cudaGetSymbolAddress((void**)&wo_l,   g_wo_l);
    cudaGetSymbolAddress((void**)&w13_h,  g_w13_h);
    cudaGetSymbolAddress((void**)&w13_l,  g_w13_l);
    cudaGetSymbolAddress((void**)&w2_h,   g_w2_h);
    cudaGetSymbolAddress((void**)&w2_l,   g_w2_l);

    float *sb_qkv, *sb_wo, *sb_w13, *sb_w2;
    cudaGetSymbolAddress((void**)&sb_qkv, g_sb_qkv);
    cudaGetSymbolAddress((void**)&sb_wo,  g_sb_wo);
    cudaGetSymbolAddress((void**)&sb_w13, g_sb_w13);
    cudaGetSymbolAddress((void**)&sb_w2,  g_sb_w2);

    cudaFuncSetAttribute(qgemm, cudaFuncAttributeMaxDynamicSharedMemorySize, QGEMM_SMEM);
    cudaFuncSetAttribute(qgemm_qkv, cudaFuncAttributeMaxDynamicSharedMemorySize, QGEMM_SMEM);
    cudaFuncSetAttribute(qgemm_swiglu, cudaFuncAttributeMaxDynamicSharedMemorySize, QGEMM_SMEM);
    cudaFuncSetAttribute(attn_mma_kernel, cudaFuncAttributeMaxDynamicSharedMemorySize, ATTN_SMEM);

    const int M = MROWS;                 // 8192
    const int DD = DMODEL * DMODEL;
    dim3 gQKV(3 * DMODEL / QBN, M / QBM);   // (48, 64)
    dim3 gD  (DMODEL / QBN,     M / QBM);   // (16, 64)
    dim3 gF13(2 * DFFN / QBN,   M / QBM);   // (64, 64)

    const float* srcs[NWJOBS] = {Wq, Wk, Wv, Wo, W1, W3, W2};
    int Ks[NWJOBS]    = {DMODEL, DMODEL, DMODEL, DMODEL, DMODEL, DMODEL, DFFN};
    int Ns[NWJOBS]    = {DMODEL, DMODEL, DMODEL, DMODEL, DFFN,   DFFN,   DMODEL};
    int modes[NWJOBS] = {0, 0, 0, 0, 1, 2, 0};
    int8_t* dsth[NWJOBS] = {wqkv_h, wqkv_h + DD, wqkv_h + 2*DD, wo_h, w13_h, w13_h, w2_h};
    int8_t* dstl[NWJOBS] = {wqkv_l, wqkv_l + DD, wqkv_l + 2*DD, wo_l, w13_l, w13_l, w2_l};
    float* sbp[NWJOBS] = {sb_qkv, sb_qkv + DMODEL, sb_qkv + 2*DMODEL, sb_wo, sb_w13, sb_w13, sb_w2};

    // 0a. weight col-max
    {
        CmJobs cj;
        int off = 0;
        for (int i = 0; i < NWJOBS; ++i) {
            cj.src[i] = srcs[i]; cj.K[i] = Ks[i]; cj.N[i] = Ns[i];
            cj.col_off[i] = off; off += Ns[i];
        }
        cj.col_off[NWJOBS] = off;
        colmax_kernel<<<off / 256, 256>>>(cj, p_cm);
    }
    // 0b. weight transpose + int8 split quant
    {
        WJobs jb;
        int off = 0, coff = 0;
        for (int i = 0; i < NWJOBS; ++i) {
            jb.src[i] = srcs[i]; jb.dsth[i] = dsth[i]; jb.dstl[i] = dstl[i];
            jb.sbp[i] = sbp[i];
            jb.K[i] = Ks[i]; jb.N[i] = Ns[i]; jb.mode[i] = modes[i];
            jb.tile_off[i] = off;
            jb.col_off[i] = coff;
            off += (Ns[i] >> 5) * (Ks[i] >> 5);
            coff += Ns[i];
        }
        jb.tile_off[NWJOBS] = off;
        wsplit_all_kernel<<<off, 256>>>(jb, p_cm);
    }

    // 1. norm1 + quant
    rmsnorm_quant_kernel<<<M, 256>>>(x, norm1_w, xn_h, xn_l, sa_xn);
    // 2. fused QKV projection -> q,k fp16 h/l + v fp16
    qgemm_qkv<<<gQKV, 256, QGEMM_SMEM>>>(xn_h, xn_l, wqkv_h, wqkv_l, sa_xn, sb_qkv,
                                         p_qkh, p_qkl, p_vh, DMODEL);
    // 3. attention (fp16-MMA scores + fp16-MMA PV) -> fp16
    attn_mma_kernel<<<M / ATQ, 256, ATTN_SMEM>>>(p_qkh, p_qkl, p_vh, p_atth);
    // 3b. quantize attention out (fp16 input)
    quant_rows_h_kernel<<<M, 256>>>(p_atth, DMODEL, att_h, att_l, sa_att);
    // 4. x_mid = x + attended @ Wo
    qgemm<<<gD, 256, QGEMM_SMEM>>>(att_h, att_l, wo_h, wo_l, sa_att, sb_wo,
                                   x, p_xmid, DMODEL, DMODEL);
    // 5. norm2 + quant
    rmsnorm_quant_kernel<<<M, 256>>>(p_xmid, norm2_w, xn2_h, xn2_l, sa_xn2);
    // 6. fused FFN up + SwiGLU -> gate fp16 [M, 2048]
    qgemm_swiglu<<<gF13, 256, QGEMM_SMEM>>>(xn2_h, xn2_l, w13_h, w13_l,
                                            sa_xn2, sb_w13, p_gateh, DMODEL);
    // 6b. quantize gate (fp16 input)
    quant_rows_h_kernel<<<M, 256>>>(p_gateh, DFFN, gate_h, gate_l, sa_gate);
    // 7. out = x_mid + gate @ W2
    qgemm<<<gD, 256, QGEMM_SMEM>>>(gate_h, gate_l, w2_h, w2_l, sa_gate, sb_w2,
                                   p_xmid, out, DMODEL, DFFN);
}

// round 17
// speedup vs baseline: 1.0530x; 1.0530x over previous
#include <cuda_runtime.h>
#include <cuda_fp16.h>
#include <cstdint>
#include <math.h>

// Problem constants
#define BATCH 4
#define SEQ   2048
#define DMODEL 1024
#define DFFN  2048
#define WIN   64
#define MROWS (BATCH*SEQ)   // 8192
#define EPS   1e-6f

// ---------------- scratch (device globals; no allocation allowed) -------------
__device__ __half g_qk_h[MROWS * 2 * DMODEL];   // q|k fp16 high [M,2048]
__device__ __half g_qk_l[MROWS * 2 * DMODEL];   // q|k fp16 low
__device__ __half g_vh  [MROWS * DMODEL];       // v fp16 [M,1024]
__device__ float  g_xmid [MROWS * DMODEL];
__device__ __half g_atth [MROWS * DMODEL];      // attention out fp16
__device__ __half g_gateh[MROWS * DFFN];        // swiglu gate fp16
// int8 split activations + per-row scales
__device__ int8_t g_xn_h [MROWS * DMODEL];
__device__ int8_t g_xn_l [MROWS * DMODEL];
__device__ int8_t g_att_h[MROWS * DMODEL];
__device__ int8_t g_att_l[MROWS * DMODEL];
__device__ int8_t g_xn2_h[MROWS * DMODEL];
__device__ int8_t g_xn2_l[MROWS * DMODEL];
__device__ int8_t g_gate_h[MROWS * DFFN];
__device__ int8_t g_gate_l[MROWS * DFFN];
__device__ float g_sa_xn [MROWS];
__device__ float g_sa_att[MROWS];
__device__ float g_sa_xn2[MROWS];
__device__ float g_sa_gate[MROWS];
// int8 split transposed weights [N,K] + per-out-row scales
__device__ int8_t g_wqkv_h[3 * DMODEL * DMODEL];
__device__ int8_t g_wqkv_l[3 * DMODEL * DMODEL];
__device__ int8_t g_wo_h  [DMODEL * DMODEL];
__device__ int8_t g_wo_l  [DMODEL * DMODEL];
__device__ int8_t g_w13_h [2 * DFFN * DMODEL];   // interleaved W1|W3
__device__ int8_t g_w13_l [2 * DFFN * DMODEL];
__device__ int8_t g_w2_h  [DMODEL * DFFN];
__device__ int8_t g_w2_l  [DMODEL * DFFN];
__device__ float g_sb_qkv[3 * DMODEL];
__device__ float g_sb_wo [DMODEL];
__device__ float g_sb_w13[2 * DFFN];
__device__ float g_sb_w2 [DMODEL];
__device__ float g_cm    [9216];                 // weight col-max scratch

// ============================= PTX helpers ====================================
__device__ __forceinline__ uint32_t smem_u32(const void* p) {
    uint32_t a;
    asm("{ .reg .u64 t; cvta.to.shared.u64 t, %1; cvt.u32.u64 %0, t; }"
        : "=r"(a) : "l"(p));
    return a;
}
__device__ __forceinline__ uint32_t swz128(uint32_t o) {  // SW128: 128B rows
    return o ^ ((o >> 3) & 0x70);
}
__device__ __forceinline__ void cpasync16(uint32_t dst, const void* src) {
    asm volatile("cp.async.cg.shared.global [%0], [%1], 16;"
                 :: "r"(dst), "l"(__cvta_generic_to_global(src)) : "memory");
}
__device__ __forceinline__ void cp_commit() {
    asm volatile("cp.async.commit_group;" ::: "memory");
}
template <int N>
__device__ __forceinline__ void cp_wait() {
    asm volatile("cp.async.wait_group %0;" :: "n"(N) : "memory");
}
__device__ __forceinline__ void ldsm_x4(uint32_t* r, uint32_t addr) {
    asm volatile("ldmatrix.sync.aligned.m8n8.x4.shared.b16 {%0,%1,%2,%3}, [%4];"
                 : "=r"(r[0]), "=r"(r[1]), "=r"(r[2]), "=r"(r[3]) : "r"(addr));
}
__device__ __forceinline__ void ldsm_x4_trans(uint32_t* r, uint32_t addr) {
    asm volatile("ldmatrix.sync.aligned.m8n8.x4.trans.shared.b16 {%0,%1,%2,%3}, [%4];"
                 : "=r"(r[0]), "=r"(r[1]), "=r"(r[2]), "=r"(r[3]) : "r"(addr));
}
// int8 MMA
__device__ __forceinline__ void mma_s8(int* c, const uint32_t* a,
                                       uint32_t b0, uint32_t b1) {
    asm("mma.sync.aligned.m16n8k32.row.col.s32.s8.s8.s32 "
        "{%0,%1,%2,%3}, {%4,%5,%6,%7}, {%8,%9}, {%0,%1,%2,%3};"
        : "+r"(c[0]), "+r"(c[1]), "+r"(c[2]), "+r"(c[3])
        : "r"(a[0]), "r"(a[1]), "r"(a[2]), "r"(a[3]), "r"(b0), "r"(b1));
}
// fp16 MMA
__device__ __forceinline__ void mma_f16(float* c, const uint32_t* a,
                                        uint32_t b0, uint32_t b1) {
    asm("mma.sync.aligned.m16n8k16.row.col.f32.f16.f16.f32 "
        "{%0,%1,%2,%3}, {%4,%5,%6,%7}, {%8,%9}, {%0,%1,%2,%3};"
        : "+f"(c[0]), "+f"(c[1]), "+f"(c[2]), "+f"(c[3])
        : "r"(a[0]), "r"(a[1]), "r"(a[2]), "r"(a[3]), "r"(b0), "r"(b1));
}

// ======== int8x3 GEMM (128x128, BK=128, 2 stages, 512 thr, 1 CTA/SM) ==========
#define QBM 128
#define QBN 128
#define QBK 128
#define QTHREADS 512
#define QAH 0
#define QAL 16384
#define QBH 32768
#define QBL 49152
#define QSTB 65536
#define QGEMM_SMEM (2 * QSTB)   // 131072

__device__ __forceinline__ void qgemm_load_stage(
    uint32_t sb,
    const int8_t* __restrict__ Ah, const int8_t* __restrict__ Al,
    const int8_t* __restrict__ Bh, const int8_t* __restrict__ Bl,
    int m0, int n0, int k0, int K, int tid)
{
    const int row = tid >> 2;            // 0..127
    const int seg = (tid & 3) * 32;      // 0,32,64,96
    const uint32_t so = row * 128 + seg;
    {   // A: 128 rows x 128B (h and l)
        const char* pAh = (const char*)(Ah + (size_t)(m0 + row) * K + k0) + seg;
        const char* pAl = (const char*)(Al + (size_t)(m0 + row) * K + k0) + seg;
        #pragma unroll
        for (int s = 0; s < 2; ++s) {
            uint32_t d = swz128(so + s * 16);
            cpasync16(sb + QAH + d, pAh + s * 16);
            cpasync16(sb + QAL + d, pAl + s * 16);
        }
    }
    {   // B: 128 rows x 128B (h and l)
        const char* pBh = (const char*)(Bh + (size_t)(n0 + row) * K + k0) + seg;
        const char* pBl = (const char*)(Bl + (size_t)(n0 + row) * K + k0) + seg;
        #pragma unroll
        for (int s = 0; s < 2; ++s) {
            uint32_t d = swz128(so + s * 16);
            cpasync16(sb + QBH + d, pBh + s * 16);
            cpasync16(sb + QBL + d, pBl + s * 16);
        }
    }
}

__device__ __forceinline__ void qgemm_mainloop(
    int (&hh)[2][4][4], int (&xx)[2][4][4],
    const int8_t* __restrict__ Ah, const int8_t* __restrict__ Al,
    const int8_t* __restrict__ Bh, const int8_t* __restrict__ Bl,
    int m0, int n0, int K, int tid, int wid, int lane, uint32_t base)
{
    const int wm0 = (wid & 3) * 32;      // 4 M-groups
    const int wn0 = (wid >> 2) * 32;     // 4 N-groups (wid 0..15)
    const int nk = K / QBK;

    #pragma unroll
    for (int i = 0; i < 2; ++i)
        #pragma unroll
        for (int j = 0; j < 4; ++j)
            #pragma unroll
            for (int t = 0; t < 4; ++t) { hh[i][j][t] = 0; xx[i][j][t] = 0; }

    qgemm_load_stage(base, Ah, Al, Bh, Bl, m0, n0, 0, K, tid);
    cp_commit();

    const uint32_t lrow  = (lane & 15);
    const uint32_t lkoff = (lane >> 4) << 4;

    for (int i = 0; i < nk; ++i) {
        cp_wait<0>();
        __syncthreads();

        const int nc = i + 1;
        if (nc < nk)
            qgemm_load_stage(base + (nc & 1) * QSTB,
                             Ah, Al, Bh, Bl, m0, n0, nc * QBK, K, tid);
        cp_commit();

        const uint32_t sb = base + (i & 1) * QSTB;
        #pragma unroll
        for (int ks = 0; ks < 4; ++ks) {
            uint32_t ah[2][4], al[2][4], bhv[2][4], blv[2][4];
            #pragma unroll
            for (int ma = 0; ma < 2; ++ma) {
                uint32_t off = (wm0 + ma * 16 + lrow) * 128 + ks * 32 + lkoff;
                uint32_t ad = sb + swz128(off);
                ldsm_x4(ah[ma], ad + QAH);
                ldsm_x4(al[ma], ad + QAL);
            }
            #pragma unroll
            for (int nt = 0; nt < 2; ++nt) {
                uint32_t off = (wn0 + nt * 16 + lrow) * 128 + ks * 32 + lkoff;
                uint32_t bd = sb + swz128(off);
                ldsm_x4(bhv[nt], bd + QBH);
                ldsm_x4(blv[nt], bd + QBL);
            }
            #pragma unroll
            for (int ma = 0; ma < 2; ++ma)
                #pragma unroll
                for (int nt = 0; nt < 2; ++nt)
                    #pragma unroll
                    for (int h = 0; h < 2; ++h) {
                        const int ng = nt * 2 + h;
                        mma_s8(hh[ma][ng], ah[ma], bhv[nt][h], bhv[nt][2 + h]);
                        mma_s8(xx[ma][ng], ah[ma], blv[nt][h], blv[nt][2 + h]);
                        mma_s8(xx[ma][ng], al[ma], bhv[nt][h], bhv[nt][2 + h]);
                    }
        }
    }
}

__device__ __forceinline__ float qcomb(int h, int x) {
    return fmaf(16384.0f, (float)h, 128.0f * (float)x);
}

__global__ __launch_bounds__(QTHREADS)
void qgemm(const int8_t* __restrict__ Ah, const int8_t* __restrict__ Al,
           const int8_t* __restrict__ Bh, const int8_t* __restrict__ Bl,
           const float* __restrict__ sa, const float* __restrict__ sb,
           const float* __restrict__ R, float* __restrict__ C,
           int N, int K)
{
    extern __shared__ char smem[];
    const int tid  = threadIdx.x;
    const int wid  = tid >> 5;
    const int lane = tid & 31;
    const int m0 = blockIdx.y * QBM;
    const int n0 = blockIdx.x * QBN;
    const uint32_t base = smem_u32(smem);

    int hh[2][4][4], xx[2][4][4];
    qgemm_mainloop(hh, xx, Ah, Al, Bh, Bl, m0, n0, K, tid, wid, lane, base);

    const int wm0 = (wid & 3) * 32;
    const int wn0 = (wid >> 2) * 32;
    const int mrow = lane >> 2;
    const int nc2  = (lane & 3) * 2;
    #pragma unroll
    for (int ma = 0; ma < 2; ++ma) {
        const int mA = m0 + wm0 + ma * 16 + mrow;
        const int mB = mA + 8;
        const float saA = sa[mA], saB = sa[mB];
        #pragma unroll
        for (int ng = 0; ng < 4; ++ng) {
            const int n = n0 + wn0 + ng * 8 + nc2;
            float2 sbv = *reinterpret_cast<const float2*>(sb + n);
            float2 v0, v1;
            v0.x = saA * sbv.x * qcomb(hh[ma][ng][0], xx[ma][ng][0]);
            v0.y = saA * sbv.y * qcomb(hh[ma][ng][1], xx[ma][ng][1]);
            v1.x = saB * sbv.x * qcomb(hh[ma][ng][2], xx[ma][ng][2]);
            v1.y = saB * sbv.y * qcomb(hh[ma][ng][3], xx[ma][ng][3]);
            size_t o0 = (size_t)mA * N + n;
            size_t o1 = (size_t)mB * N + n;
            if (R) {
                float2 r0 = *reinterpret_cast<const float2*>(R + o0);
                float2 r1 = *reinterpret_cast<const float2*>(R + o1);
                v0.x += r0.x; v0.y += r0.y;
                v1.x += r1.x; v1.y += r1.y;
            }
            *reinterpret_cast<float2*>(C + o0) = v0;
            *reinterpret_cast<float2*>(C + o1) = v1;
        }
    }
}

// QKV GEMM: q,k columns (n<2048) -> fp16 h/l pairs; v columns -> fp16 single.
__global__ __launch_bounds__(QTHREADS)
void qgemm_qkv(const int8_t* __restrict__ Ah, const int8_t* __restrict__ Al,
               const int8_t* __restrict__ Bh, const int8_t* __restrict__ Bl,
               const float* __restrict__ sa, const float* __restrict__ sb,
               __half* __restrict__ qkh, __half* __restrict__ qkl,
               __half* __restrict__ vh, int K)
{
    extern __shared__ char smem[];
    const int tid  = threadIdx.x;
    const int wid  = tid >> 5;
    const int lane = tid & 31;
    const int m0 = blockIdx.y * QBM;
    const int n0 = blockIdx.x * QBN;
    const uint32_t base = smem_u32(smem);

    int hh[2][4][4], xx[2][4][4];
    qgemm_mainloop(hh, xx, Ah, Al, Bh, Bl, m0, n0, K, tid, wid, lane, base);

    const int wm0 = (wid & 3) * 32;
    const int wn0 = (wid >> 2) * 32;
    const int mrow = lane >> 2;
    const int nc2  = (lane & 3) * 2;
    const bool isv = (n0 >= 2048);
    #pragma unroll
    for (int ma = 0; ma < 2; ++ma) {
        const int mA = m0 + wm0 + ma * 16 + mrow;
        const int mB = mA + 8;
        const float saA = sa[mA], saB = sa[mB];
        #pragma unroll
        for (int ng = 0; ng < 4; ++ng) {
            const int n = n0 + wn0 + ng * 8 + nc2;
            float2 sbv = *reinterpret_cast<const float2*>(sb + n);
            float2 v0, v1;
            v0.x = saA * sbv.x * qcomb(hh[ma][ng][0], xx[ma][ng][0]);
            v0.y = saA * sbv.y * qcomb(hh[ma][ng][1], xx[ma][ng][1]);
            v1.x = saB * sbv.x * qcomb(hh[ma][ng][2], xx[ma][ng][2]);
            v1.y = saB * sbv.y * qcomb(hh[ma][ng][3], xx[ma][ng][3]);
            if (!isv) {
                size_t o0 = (size_t)mA * 2048 + n;
                size_t o1 = (size_t)mB * 2048 + n;
                __half2 h0, l0, h1, l1;
                h0.x = __float2half_rn(v0.x); h0.y = __float2half_rn(v0.y);
                l0.x = __float2half_rn(v0.x - __half2float(h0.x));
                l0.y = __float2half_rn(v0.y - __half2float(h0.y));
                h1.x = __float2half_rn(v1.x); h1.y = __float2half_rn(v1.y);
                l1.x = __float2half_rn(v1.x - __half2float(h1.x));
                l1.y = __float2half_rn(v1.y - __half2float(h1.y));
                *reinterpret_cast<__half2*>(qkh + o0) = h0;
                *reinterpret_cast<__half2*>(qkl + o0) = l0;
                *reinterpret_cast<__half2*>(qkh + o1) = h1;
                *reinterpret_cast<__half2*>(qkl + o1) = l1;
            } else {
                size_t o0 = (size_t)mA * 1024 + (n - 2048);
                size_t o1 = (size_t)mB * 1024 + (n - 2048);
                __half2 a, bq;
                a.x  = __float2half_rn(v0.x); a.y  = __float2half_rn(v0.y);
                bq.x = __float2half_rn(v1.x); bq.y = __float2half_rn(v1.y);
                *reinterpret_cast<__half2*>(vh + o0) = a;
                *reinterpret_cast<__half2*>(vh + o1) = bq;
            }
        }
    }
}

// W13 interleaved + fused SwiGLU: writes gate fp16 [M, DFFN].
__global__ __launch_bounds__(QTHREADS)
void qgemm_swiglu(const int8_t* __restrict__ Ah, const int8_t* __restrict__ Al,
                  const int8_t* __restrict__ Bh, const int8_t* __restrict__ Bl,
                  const float* __restrict__ sa, const float* __restrict__ sb,
                  __half* __restrict__ gate, int K)
{
    extern __shared__ char smem[];
    const int tid  = threadIdx.x;
    const int wid  = tid >> 5;
    const int lane = tid & 31;
    const int m0 = blockIdx.y * QBM;
    const int n0 = blockIdx.x * QBN;
    const uint32_t base = smem_u32(smem);

    int hh[2][4][4], xx[2][4][4];
    qgemm_mainloop(hh, xx, Ah, Al, Bh, Bl, m0, n0, K, tid, wid, lane, base);

    const int wm0 = (wid & 3) * 32;
    const int wn0 = (wid >> 2) * 32;
    const int mrow = lane >> 2;
    const int nc2  = (lane & 3) * 2;
    const int gbase = (n0 + wn0) >> 1;
    #pragma unroll
    for (int ma = 0; ma < 2; ++ma) {
        const int mA = m0 + wm0 + ma * 16 + mrow;
        const int mB = mA + 8;
        const float saA = sa[mA], saB = sa[mB];
        #pragma unroll
        for (int g = 0; g < 2; ++g) {
            const int p1 = n0 + wn0 + 16 * g + nc2;
            const int p3 = p1 + 8;
            float2 sb1 = *reinterpret_cast<const float2*>(sb + p1);
            float2 sb3 = *reinterpret_cast<const float2*>(sb + p3);
            const int gcol = gbase + 8 * g + nc2;
            const int n1 = 2 * g, n3 = 2 * g + 1;
            {
                float a0 = saA * sb1.x * qcomb(hh[ma][n1][0], xx[ma][n1][0]);
                float a1 = saA * sb1.y * qcomb(hh[ma][n1][1], xx[ma][n1][1]);
                float c0 = saA * sb3.x * qcomb(hh[ma][n3][0], xx[ma][n3][0]);
                float c1 = saA * sb3.y * qcomb(hh[ma][n3][1], xx[ma][n3][1]);
                __half2 o;
                o.x = __float2half_rn(a0 / (1.0f + __expf(-a0)) * c0);
                o.y = __float2half_rn(a1 / (1.0f + __expf(-a1)) * c1);
                *reinterpret_cast<__half2*>(gate + (size_t)mA * DFFN + gcol) = o;
            }
            {
                float a0 = saB * sb1.x * qcomb(hh[ma][n1][2], xx[ma][n1][2]);
                float a1 = saB * sb1.y * qcomb(hh[ma][n1][3], xx[ma][n1][3]);
                float c0 = saB * sb3.x * qcomb(hh[ma][n3][2], xx[ma][n3][2]);
                float c1 = saB * sb3.y * qcomb(hh[ma][n3][3], xx[ma][n3][3]);
                __half2 o;
                o.x = __float2half_rn(a0 / (1.0f + __expf(-a0)) * c0);
                o.y = __float2half_rn(a1 / (1.0f + __expf(-a1)) * c1);
                *reinterpret_cast<__half2*>(gate + (size_t)mB * DFFN + gcol) = o;
            }
        }
    }
}

// ---------------- 15-bit quantization helper ----------------------------------
__device__ __forceinline__ void quant15(float v, float invq, int8_t& h, int8_t& l) {
    float t  = rintf(v * invq);
    float th = rintf(t * 0.0078125f);
    h = (int8_t)(int)th;
    l = (int8_t)(int)(t - 128.0f * th);
}

// ============ weight col-max, 7 jobs ==========================================
#define NWJOBS 7
struct CmJobs {
    const float* src[NWJOBS];
    int K[NWJOBS];
    int N[NWJOBS];
    int col_off[NWJOBS + 1];
};
__global__ void colmax_kernel(CmJobs jb, float* cm)
{
    int c = blockIdx.x * 256 + threadIdx.x;
    int j = 0;
    #pragma unroll
    for (int i = 0; i < NWJOBS; ++i)
        if (c >= jb.col_off[i + 1]) j = i + 1;
    const int n = c - jb.col_off[j];
    const int K = jb.K[j], N = jb.N[j];
    const float* W = jb.src[j];
    float m = 0.0f;
    for (int k = 0; k < K; ++k)
        m = fmaxf(m, fabsf(W[(size_t)k * N + n]));
    cm[c] = m;
}

// ============ weight transpose + int8 split quant =============================
struct WJobs {
    const float* src[NWJOBS];
    int8_t* dsth[NWJOBS];
    int8_t* dstl[NWJOBS];
    float* sbp[NWJOBS];
    int K[NWJOBS];
    int N[NWJOBS];
    int mode[NWJOBS];
    int tile_off[NWJOBS + 1];
    int col_off[NWJOBS];
};
__global__ void wsplit_all_kernel(WJobs jb, const float* cm)
{
    __shared__ float t[32][33];
    int tile = blockIdx.x;
    int j = 0;
    #pragma unroll
    for (int i = 0; i < NWJOBS; ++i)
        if (tile >= jb.tile_off[i + 1]) j = i + 1;
    const int lt   = tile - jb.tile_off[j];
    const int K    = jb.K[j];
    const int N    = jb.N[j];
    const int mode = jb.mode[j];
    const float* W = jb.src[j];
    int8_t* Th     = jb.dsth[j];
    int8_t* Tl     = jb.dstl[j];
    const int ntx  = N >> 5;
    const int n0 = (lt % ntx) * 32;
    const int k0 = (lt / ntx) * 32;

    int tx = threadIdx.x & 31, ty = threadIdx.x >> 5;
    #pragma unroll
    for (int r = ty; r < 32; r += 8)
        t[r][tx] = W[(size_t)(k0 + r) * N + n0 + tx];
    __syncthreads();
    #pragma unroll
    for (int r = ty; r < 32; r += 8) {
        float v = t[tx][r];
        int n = n0 + r;
        int p = (mode == 0) ? n : (16 * (n >> 3) + (n & 7) + ((mode == 2) ? 8 : 0));
        float mx = cm[jb.col_off[j] + n];
        float invq = (mx > 0.0f) ? (16256.0f / mx) : 0.0f;
        int8_t h, l;
        quant15(v, invq, h, l);
        size_t o = (size_t)p * K + k0 + tx;
        Th[o] = h; Tl[o] = l;
        if (k0 + tx == 0) jb.sbp[j][p] = mx * (1.0f / 16256.0f);
    }
}

// ---------------- RMSNorm + int8 split quant ----------------------------------
__global__ void rmsnorm_quant_kernel(const float* __restrict__ x,
                                     const float* __restrict__ w,
                                     int8_t* __restrict__ oh,
                                     int8_t* __restrict__ ol,
                                     float* __restrict__ sa) {
    const int D = DMODEL;
    size_t row = blockIdx.x;
    const float4* xr = reinterpret_cast<const float4*>(x + row * D);
    const float4* wr = reinterpret_cast<const float4*>(w);

    int tid = threadIdx.x;
    float4 xv = xr[tid];
    float4 wv = wr[tid];
    float p0 = xv.x * wv.x, p1 = xv.y * wv.y, p2 = xv.z * wv.z, p3 = xv.w * wv.w;
    float ss = xv.x*xv.x + xv.y*xv.y + xv.z*xv.z + xv.w*xv.w;
    float mx = fmaxf(fmaxf(fabsf(p0), fabsf(p1)), fmaxf(fabsf(p2), fabsf(p3)));

    #pragma unroll
    for (int off = 16; off; off >>= 1) {
        ss += __shfl_xor_sync(0xffffffffu, ss, off);
        mx = fmaxf(mx, __shfl_xor_sync(0xffffffffu, mx, off));
    }
    __shared__ float reds[8], redm[8];
    int lane = tid & 31, warp = tid >> 5;
    if (lane == 0) { reds[warp] = ss; redm[warp] = mx; }
    __syncthreads();
    if (tid < 32) {
        float v = (tid < 8) ? reds[tid] : 0.0f;
        float m = (tid < 8) ? redm[tid] : 0.0f;
        #pragma unroll
        for (int off = 4; off; off >>= 1) {
            v += __shfl_xor_sync(0xffffffffu, v, off);
            m = fmaxf(m, __shfl_xor_sync(0xffffffffu, m, off));
        }
        if (tid == 0) {
            float inv = rsqrtf(v * (1.0f / D) + EPS);
            reds[0] = inv;
            redm[0] = m;
            sa[row] = inv * m * (1.0f / 16256.0f);
        }
    }
    __syncthreads();
    float m = redm[0];
    float invq = (m > 0.0f) ? (16256.0f / m) : 0.0f;

    int8_t hv[4], lv[4];
    quant15(p0, invq, hv[0], lv[0]);
    quant15(p1, invq, hv[1], lv[1]);
    quant15(p2, invq, hv[2], lv[2]);
    quant15(p3, invq, hv[3], lv[3]);
    size_t b = row * D + tid * 4;
    *reinterpret_cast<char4*>(oh + b) = make_char4(hv[0], hv[1], hv[2], hv[3]);
    *reinterpret_cast<char4*>(ol + b) = make_char4(lv[0], lv[1], lv[2], lv[3]);
}

// ---------------- per-row quant pass (fp16 input) ------------------------------
__global__ void quant_rows_h_kernel(const __half* __restrict__ src, int D,
                                    int8_t* __restrict__ oh, int8_t* __restrict__ ol,
                                    float* __restrict__ sa)
{
    size_t row = blockIdx.x;
    const uint2* sr = reinterpret_cast<const uint2*>(src + row * D);  // 4 halves
    int tid = threadIdx.x;
    const int iters = D / 1024;   // 1 or 2

    float f[2][4];
    float mx = 0.0f;
    #pragma unroll
    for (int it = 0; it < 2; ++it) {
        if (it < iters) {
            uint2 u = sr[tid + it * 256];
            __half2 a = *reinterpret_cast<__half2*>(&u.x);
            __half2 b = *reinterpret_cast<__half2*>(&u.y);
            f[it][0] = __half2float(a.x); f[it][1] = __half2float(a.y);
            f[it][2] = __half2float(b.x); f[it][3] = __half2float(b.y);
            mx = fmaxf(mx, fmaxf(fmaxf(fabsf(f[it][0]), fabsf(f[it][1])),
                                 fmaxf(fabsf(f[it][2]), fabsf(f[it][3]))));
        }
    }
    #pragma unroll
    for (int off = 16; off; off >>= 1)
        mx = fmaxf(mx, __shfl_xor_sync(0xffffffffu, mx, off));
    __shared__ float redm[8];
    int lane = tid & 31, warp = tid >> 5;
    if (lane == 0) redm[warp] = mx;
    __syncthreads();
    if (tid < 32) {
        float m = (tid < 8) ? redm[tid] : 0.0f;
        #pragma unroll
        for (int off = 4; off; off >>= 1)
            m = fmaxf(m, __shfl_xor_sync(0xffffffffu, m, off));
        if (tid == 0) {
            redm[0] = m;
            sa[row] = m * (1.0f / 16256.0f);
        }
    }
    __syncthreads();
    float m = redm[0];
    float invq = (m > 0.0f) ? (16256.0f / m) : 0.0f;

    #pragma unroll
    for (int it = 0; it < 2; ++it) {
        if (it < iters) {
            int8_t hv[4], lv[4];
            quant15(f[it][0], invq, hv[0], lv[0]);
            quant15(f[it][1], invq, hv[1], lv[1]);
            quant15(f[it][2], invq, hv[2], lv[2]);
            quant15(f[it][3], invq, hv[3], lv[3]);
            size_t b = row * D + (tid + it * 256) * 4;
            *reinterpret_cast<char4*>(oh + b) = make_char4(hv[0], hv[1], hv[2], hv[3]);
            *reinterpret_cast<char4*>(ol + b) = make_char4(lv[0], lv[1], lv[2], lv[3]);
        }
    }
}

// ---------------- Attention: fp16-MMA scores + fp16-MMA PV --------------------
#define ATQ   32
#define ASPAD 132
#define AS_BYTES (ATQ * ASPAD * 4)
#define AP_OFF  16896                  // P fp16 [32][136] pitch 272B
#define AST_OFF 25600                  // stage area (2 x 40960)
#define ASTG  40960
#define AQH 0
#define AQL 4096
#define AKH 8192
#define AKL 24576
#define ATTN_SMEM (AST_OFF + 2 * ASTG)   // 107520 B

__device__ __forceinline__ void attn_load_chunk(
    uint32_t st, const __half* __restrict__ qkh, const __half* __restrict__ qkl,
    size_t rowbase, int t0, int jlo, int span, int dc, int tid)
{
    const int d0 = dc * 64;
    {
        const int row = tid >> 3;
        const int seg = (tid & 7) * 16;
        const uint32_t d = swz128(row * 128 + seg);
        const char* ph = (const char*)(qkh + (rowbase + t0 + row) * 2048 + d0) + seg;
        const char* pl = (const char*)(qkl + (rowbase + t0 + row) * 2048 + d0) + seg;
        cpasync16(st + AQH + d, ph);
        cpasync16(st + AQL + d, pl);
    }
    {
        const int seg = (tid & 7) * 16;
        for (int r = tid >> 3; r < span; r += 32) {
            const uint32_t d = swz128(r * 128 + seg);
            const char* ph = (const char*)(qkh + (rowbase + jlo + r) * 2048 + 1024 + d0) + seg;
            const char* pl = (const char*)(qkl + (rowbase + jlo + r) * 2048 + 1024 + d0) + seg;
            cpasync16(st + AKH + d, ph);
            cpasync16(st + AKL + d, pl);
        }
    }
}

__device__ __forceinline__ void attn_load_v(
    uint32_t vb, const __half* __restrict__ vh,
    size_t rowbase, int jlo, int span, int d0, int tid)
{
    for (int idx = tid; idx < span * 16; idx += 256) {
        const int r = idx >> 4;
        const int s = idx & 15;
        const char* p = (const char*)(vh + (rowbase + jlo + r) * 1024 + d0) + s * 16;
        cpasync16(vb + r * 272 + s * 16, p);
    }
}

__global__ __launch_bounds__(256)
void attn_mma_kernel(const __half* __restrict__ qkh, const __half* __restrict__ qkl,
                     const __half* __restrict__ vh, __half* __restrict__ atth)
{
    extern __shared__ char smraw[];
    float* S = (float*)smraw;
    const uint32_t smb = smem_u32(smraw);
    const uint32_t sbase = smb + AST_OFF;

    const int tid  = threadIdx.x;
    const int wid  = tid >> 5;
    const int lane = tid & 31;
    const int blk  = blockIdx.x;
    const int b    = blk >> 6;
    const int t0   = (blk & 63) * ATQ;
    const int jlo  = (t0 >= WIN) ? (t0 - (WIN - 1)) : 0;   // clamped
    const int span = t0 + ATQ - jlo;          // 32, 64, or 95
    const size_t rowbase = (size_t)b * SEQ;
    const float scale = 0.03125f;

    // ---- phase 1: scores via fp16x3 mma ----
    const int wm = (wid & 1) * 16;
    const int wn = (wid >> 1) * 32;
    const uint32_t lrow  = (lane & 15);
    const uint32_t lkoff = (lane >> 4) << 4;

    float acc[4][4];
    #pragma unroll
    for (int i = 0; i < 4; ++i)
        #pragma unroll
        for (int t = 0; t < 4; ++t) acc[i][t] = 0.0f;

    attn_load_chunk(sbase, qkh, qkl, rowbase, t0, jlo, span, 0, tid);
    cp_commit();

    for (int dc = 0; dc < 16; ++dc) {
        cp_wait<0>();
        __syncthreads();
        if (dc + 1 < 16) {
            attn_load_chunk(sbase + ((dc + 1) & 1) * ASTG,
                            qkh, qkl, rowbase, t0, jlo, span, dc + 1, tid);
            cp_commit();
        }
        const uint32_t st = sbase + (dc & 1) * ASTG;
        #pragma unroll
        for (int ks = 0; ks < 4; ++ks) {
            uint32_t ah[4], al[4], bh[2][4], bl[2][4];
            uint32_t offA = (wm + lrow) * 128 + ks * 32 + lkoff;
            ldsm_x4(ah, st + AQH + swz128(offA));
            ldsm_x4(al, st + AQL + swz128(offA));
            #pragma unroll
            for (int nt = 0; nt < 2; ++nt) {
                uint32_t offB = (wn + nt * 16 + lrow) * 128 + ks * 32 + lkoff;
                ldsm_x4(bh[nt], st + AKH + swz128(offB));
                ldsm_x4(bl[nt], st + AKL + swz128(offB));
            }
            #pragma unroll
            for (int nt = 0; nt < 2; ++nt)
                #pragma unroll
                for (int h = 0; h < 2; ++h) {
                    const int ng = nt * 2 + h;
                    mma_f16(acc[ng], ah, bh[nt][h], bh[nt][2 + h]);
                    mma_f16(acc[ng], ah, bl[nt][h], bl[nt][2 + h]);
                    mma_f16(acc[ng], al, bh[nt][h], bh[nt][2 + h]);
                }
        }
    }

    // store scores to S
    {
        const int mrow = lane >> 2;
        const int nc2  = (lane & 3) * 2;
        #pragma unroll
        for (int ng = 0; ng < 4; ++ng) {
            const int n = wn + ng * 8 + nc2;
            S[(wm + mrow    ) * ASPAD + n    ] = acc[ng][0] * scale;
            S[(wm + mrow    ) * ASPAD + n + 1] = acc[ng][1] * scale;
            S[(wm + mrow + 8) * ASPAD + n    ] = acc[ng][2] * scale;
            S[(wm + mrow + 8) * ASPAD + n + 1] = acc[ng][3] * scale;
        }
    }
    __syncthreads();

    // ---- phase 2: softmax + write P fp16 ----
    if (tid < ATQ) {
        const int qi  = tid;
        const int ti  = t0 + qi;
        const int wlo = ((ti >= WIN - 1) ? ti - (WIN - 1) : 0) - jlo;
        const int whi = ti - jlo;
        float* row = S + qi * ASPAD;
        float m = -1e30f;
        for (int jj = wlo; jj <= whi; ++jj) m = fmaxf(m, row[jj]);
        float sum = 0.0f;
        for (int jj = wlo; jj <= whi; ++jj) {
            float e = __expf(row[jj] - m);
            row[jj] = e;
            sum += e;
        }
        float inv = 1.0f / sum;
        __half* Prow = (__half*)(smraw + AP_OFF) + qi * 136;
        for (int jj = 0; jj < 128; ++jj) {
            float p = (jj >= wlo && jj <= whi) ? row[jj] * inv : 0.0f;
            Prow[jj] = __float2half_rn(p);
        }
    }
    __syncthreads();

    // ---- phase 3: PV via fp16 mma ----
    {
        float4 z = make_float4(0.f, 0.f, 0.f, 0.f);
        const int npad = 128 - span;
        for (int idx = tid; idx < npad * 34; idx += 256) {
            int bufr = idx / 17;
            int s    = idx % 17;
            int buf  = bufr & 1;
            int r    = span + (bufr >> 1);
            *reinterpret_cast<float4*>(smraw + AST_OFF + buf * ASTG + r * 272 + s * 16) = z;
        }
    }
    attn_load_v(sbase, vh, rowbase, jlo, span, 0, tid);
    cp_commit();

    const uint32_t Pbase = smb + AP_OFF;
    const int wmP = (wid & 1) * 16;
    const int wnV = (wid >> 1) * 32;

    for (int vc = 0; vc < 8; ++vc) {
        cp_wait<0>();
        __syncthreads();
        if (vc + 1 < 8) {
            attn_load_v(sbase + ((vc + 1) & 1) * ASTG,
                        vh, rowbase, jlo, span, (vc + 1) * 128, tid);
            cp_commit();
        }
        const uint32_t Vb = sbase + (vc & 1) * ASTG;

        float oacc[4][4];
        #pragma unroll
        for (int i = 0; i < 4; ++i)
            #pragma unroll
            for (int t = 0; t < 4; ++t) oacc[i][t] = 0.0f;

        #pragma unroll
        for (int ks = 0; ks < 8; ++ks) {
            uint32_t ap[4];
            ldsm_x4(ap, Pbase + (wmP + (lane & 15)) * 272 + ks * 32 + ((lane >> 4) << 4));
            uint32_t bt[2][4];
            #pragma unroll
            for (int nt = 0; nt < 2; ++nt)
                ldsm_x4_trans(bt[nt],
                    Vb + (ks * 16 + (lane & 15)) * 272 + (wnV + nt * 16) * 2 + ((lane >> 4) << 4));
            #pragma unroll
            for (int nt = 0; nt < 2; ++nt) {
                mma_f16(oacc[nt * 2],     ap, bt[nt][0], bt[nt][1]);
                mma_f16(oacc[nt * 2 + 1], ap, bt[nt][2], bt[nt][3]);
            }
        }

        const int mrow = lane >> 2;
        const int nc2  = (lane & 3) * 2;
        #pragma unroll
        for (int ng = 0; ng < 4; ++ng) {
            const int d = vc * 128 + wnV + ng * 8 + nc2;
            size_t o0 = (rowbase + t0 + wmP + mrow) * DMODEL + d;
            size_t o1 = o0 + (size_t)8 * DMODEL;
            __half2 h0, h1;
            h0.x = __float2half_rn(oacc[ng][0]); h0.y = __float2half_rn(oacc[ng][1]);
            h1.x = __float2half_rn(oacc[ng][2]); h1.y = __float2half_rn(oacc[ng][3]);
            *reinterpret_cast<__half2*>(atth + o0) = h0;
            *reinterpret_cast<__half2*>(atth + o1) = h1;
        }
    }
}

// ---------------- launch -------------------------------------------------------
extern "C" void kernel_launch(void* const* d_in, const int* in_sizes, int n_in,
                              void* d_out, int out_size) {
    const float* x       = (const float*)d_in[0];
    const float* norm1_w = (const float*)d_in[1];
    const float* norm2_w = (const float*)d_in[2];
    const float* Wq      = (const float*)d_in[3];
    const float* Wk      = (const float*)d_in[4];
    const float* Wv      = (const float*)d_in[5];
    const float* Wo      = (const float*)d_in[6];
    const float* W1      = (const float*)d_in[7];
    const float* W2      = (const float*)d_in[8];
    const float* W3      = (const float*)d_in[9];
    float* out = (float*)d_out;

    float *p_xmid, *p_cm;
    __half *p_qkh, *p_qkl, *p_vh, *p_atth, *p_gateh;
    cudaGetSymbolAddress((void**)&p_qkh,   g_qk_h);
    cudaGetSymbolAddress((void**)&p_qkl,   g_qk_l);
    cudaGetSymbolAddress((void**)&p_vh,    g_vh);
    cudaGetSymbolAddress((void**)&p_xmid,  g_xmid);
    cudaGetSymbolAddress((void**)&p_atth,  g_atth);
    cudaGetSymbolAddress((void**)&p_gateh, g_gateh);
    cudaGetSymbolAddress((void**)&p_cm,    g_cm);

    int8_t *xn_h, *xn_l, *att_h, *att_l, *xn2_h, *xn2_l, *gate_h, *gate_l;
    cudaGetSymbolAddress((void**)&xn_h,  g_xn_h);
    cudaGetSymbolAddress((void**)&xn_l,  g_xn_l);
    cudaGetSymbolAddress((void**)&att_h, g_att_h);
    cudaGetSymbolAddress((void**)&att_l, g_att_l);
    cudaGetSymbolAddress((void**)&xn2_h, g_xn2_h);
    cudaGetSymbolAddress((void**)&xn2_l, g_xn2_l);
    cudaGetSymbolAddress((void**)&gate_h, g_gate_h);
    cudaGetSymbolAddress((void**)&gate_l, g_gate_l);

    float *sa_xn, *sa_att, *sa_xn2, *sa_gate;
    cudaGetSymbolAddress((void**)&sa_xn,   g_sa_xn);
    cudaGetSymbolAddress((void**)&sa_att,  g_sa_att);
    cudaGetSymbolAddress((void**)&sa_xn2,  g_sa_xn2);
    cudaGetSymbolAddress((void**)&sa_gate, g_sa_gate);

    int8_t *wqkv_h, *wqkv_l, *wo_h, *wo_l, *w13_h, *w13_l, *w2_h, *w2_l;
    cudaGetSymbolAddress((void**)&wqkv_h, g_wqkv_h);
    cudaGetSymbolAddress((void**)&wqkv_l, g_wqkv_l);
    cudaGetSymbolAddress((void**)&wo_h,   g_wo_h);
    cudaGetSymbolAddress((void**)&wo_l,   g_wo_l);
    cudaGetSymbolAddress((void**)&w13_h,  g_w13_h);
    cudaGetSymbolAddress((void**)&w13_l,  g_w13_l);
    cudaGetSymbolAddress((void**)&w2_h,   g_w2_h);
    cudaGetSymbolAddress((void**)&w2_l,   g_w2_l);

    float *sb_qkv, *sb_wo, *sb_w13, *sb_w2;
    cudaGetSymbolAddress((void**)&sb_qkv, g_sb_qkv);
    cudaGetSymbolAddress((void**)&sb_wo,  g_sb_wo);
    cudaGetSymbolAddress((void**)&sb_w13, g_sb_w13);
    cudaGetSymbolAddress((void**)&sb_w2,  g_sb_w2);

    cudaFuncSetAttribute(qgemm, cudaFuncAttributeMaxDynamicSharedMemorySize, QGEMM_SMEM);
    cudaFuncSetAttribute(qgemm_qkv, cudaFuncAttributeMaxDynamicSharedMemorySize, QGEMM_SMEM);
    cudaFuncSetAttribute(qgemm_swiglu, cudaFuncAttributeMaxDynamicSharedMemorySize, QGEMM_SMEM);
    cudaFuncSetAttribute(attn_mma_kernel, cudaFuncAttributeMaxDynamicSharedMemorySize, ATTN_SMEM);

    const int M = MROWS;                 // 8192
    const int DD = DMODEL * DMODEL;
    dim3 gQKV(3 * DMODEL / QBN, M / QBM);   // (24, 64)
    dim3 gD  (DMODEL / QBN,     M / QBM);   // (8, 64)
    dim3 gF13(2 * DFFN / QBN,   M / QBM);   // (32, 64)

    const float* srcs[NWJOBS] = {Wq, Wk, Wv, Wo, W1, W3, W2};
    int Ks[NWJOBS]    = {DMODEL, DMODEL, DMODEL, DMODEL, DMODEL, DMODEL, DFFN};
    int Ns[NWJOBS]    = {DMODEL, DMODEL, DMODEL, DMODEL, DFFN,   DFFN,   DMODEL};
    int modes[NWJOBS] = {0, 0, 0, 0, 1, 2, 0};
    int8_t* dsth[NWJOBS] = {wqkv_h, wqkv_h + DD, wqkv_h + 2*DD, wo_h, w13_h, w13_h, w2_h};
    int8_t* dstl[NWJOBS] = {wqkv_l, wqkv_l + DD, wqkv_l + 2*DD, wo_l, w13_l, w13_l, w2_l};
    float* sbp[NWJOBS] = {sb_qkv, sb_qkv + DMODEL, sb_qkv + 2*DMODEL, sb_wo, sb_w13, sb_w13, sb_w2};

    // 0a. weight col-max
    {
        CmJobs cj;
        int off = 0;
        for (int i = 0; i < NWJOBS; ++i) {
            cj.src[i] = srcs[i]; cj.K[i] = Ks[i]; cj.N[i] = Ns[i];
            cj.col_off[i] = off; off += Ns[i];
        }
        cj.col_off[NWJOBS] = off;
        colmax_kernel<<<off / 256, 256>>>(cj, p_cm);
    }
    // 0b. weight transpose + int8 split quant
    {
        WJobs jb;
        int off = 0, coff = 0;
        for (int i = 0; i < NWJOBS; ++i) {
            jb.src[i] = srcs[i]; jb.dsth[i] = dsth[i]; jb.dstl[i] = dstl[i];
            jb.sbp[i] = sbp[i];
            jb.K[i] = Ks[i]; jb.N[i] = Ns[i]; jb.mode[i] = modes[i];
            jb.tile_off[i] = off;
            jb.col_off[i] = coff;
            off += (Ns[i] >> 5) * (Ks[i] >> 5);
            coff += Ns[i];
        }
        jb.tile_off[NWJOBS] = off;
        wsplit_all_kernel<<<off, 256>>>(jb, p_cm);
    }

    // 1. norm1 + quant
    rmsnorm_quant_kernel<<<M, 256>>>(x, norm1_w, xn_h, xn_l, sa_xn);
    // 2. fused QKV projection -> q,k fp16 h/l + v fp16
    qgemm_qkv<<<gQKV, QTHREADS, QGEMM_SMEM>>>(xn_h, xn_l, wqkv_h, wqkv_l, sa_xn, sb_qkv,
                                              p_qkh, p_qkl, p_vh, DMODEL);
    // 3. attention (fp16-MMA scores + fp16-MMA PV) -> fp16
    attn_mma_kernel<<<M / ATQ, 256, ATTN_SMEM>>>(p_qkh, p_qkl, p_vh, p_atth);
    // 3b. quantize attention out (fp16 input)
    quant_rows_h_kernel<<<M, 256>>>(p_atth, DMODEL, att_h, att_l, sa_att);
    // 4. x_mid = x + attended @ Wo
    qgemm<<<gD, QTHREADS, QGEMM_SMEM>>>(att_h, att_l, wo_h, wo_l, sa_att, sb_wo,
                                        x, p_xmid, DMODEL, DMODEL);
    // 5. norm2 + quant
    rmsnorm_quant_kernel<<<M, 256>>>(p_xmid, norm2_w, xn2_h, xn2_l, sa_xn2);
    // 6. fused FFN up + SwiGLU -> gate fp16 [M, 2048]
    qgemm_swiglu<<<gF13, QTHREADS, QGEMM_SMEM>>>(xn2_h, xn2_l, w13_h, w13_l,
                                                 sa_xn2, sb_w13, p_gateh, DMODEL);
    // 6b. quantize gate (fp16 input)
    quant_rows_h_kernel<<<M, 256>>>(p_gateh, DFFN, gate_h, gate_l, sa_gate);
    // 7. out = x_mid + gate @ W2
    qgemm<<<gD, QTHREADS, QGEMM_SMEM>>>(gate_h, gate_l, w2_h, w2_l, sa_gate, sb_w2,
                                        p_xmid, out, DMODEL, DFFN);
}